// round 1
// baseline (speedup 1.0000x reference)
#include <cuda_runtime.h>
#include <cstdint>

// Problem constants (fixed shapes for this problem)
#define NTOT 32768          // total nodes N = G*n
#define FDIM 128            // input features
#define EMBD 32             // embedding dim
#define NG   32             // num graphs
#define NPG  1024           // nodes per graph
// Output layout (all float32):
//   [0, 1048576)                      xe  (32768 x 32)
//   [1048576, 1048576+33554432)       src (edge_index row 0, as float)
//   [.., +33554432)                   dst (edge_index row 1, as float)
//   [.., +33554432)                   edge_weight
#define OFF_SRC 1048576u
#define OFF_DST 34603008u
#define OFF_EW  68157440u

// Scratch (device globals: no allocation allowed)
__device__ float g_xgT[NG * EMBD * NPG];   // [g][k][i] transposed normalized embeddings
__device__ float g_sq[NTOT];               // per-row squared norms of xg
__device__ float g_stats[33];              // [0..31]=centroid, [32]=scale

// ---------------------------------------------------------------------------
// packed f32x2 helpers (sm_100+)
// ---------------------------------------------------------------------------
__device__ __forceinline__ unsigned long long pack2(float lo, float hi) {
    unsigned long long r;
    asm("mov.b64 %0, {%1, %2};" : "=l"(r) : "f"(lo), "f"(hi));
    return r;
}
__device__ __forceinline__ void unpack2(unsigned long long v, float& lo, float& hi) {
    asm("mov.b64 {%0, %1}, %2;" : "=f"(lo), "=f"(hi) : "l"(v));
}
__device__ __forceinline__ unsigned long long ffma2(unsigned long long a,
                                                    unsigned long long b,
                                                    unsigned long long c) {
    unsigned long long d;
    asm("fma.rn.f32x2 %0, %1, %2, %3;" : "=l"(d) : "l"(a), "l"(b), "l"(c));
    return d;
}

// ---------------------------------------------------------------------------
// K1: xe = x @ W   (32768x128 @ 128x32) -> d_out[0 : 1048576)
// Block: 256 threads, 32 rows per block. W and x-rows staged in smem.
// ---------------------------------------------------------------------------
__global__ __launch_bounds__(256) void k1_gemm(const float* __restrict__ x,
                                               const float* __restrict__ W,
                                               float* __restrict__ xe) {
    __shared__ float ws[FDIM * EMBD];      // 16 KB, row-major [k][d]
    __shared__ float xs[32 * FDIM];        // 16 KB, [r][k]
    const int t = threadIdx.x;
    const int row0 = blockIdx.x * 32;

    for (int e = t; e < FDIM * EMBD; e += 256) ws[e] = W[e];
    // 32 rows * 128 floats = 1024 float4
    for (int e = t; e < 1024; e += 256) {
        ((float4*)xs)[e] = ((const float4*)(x + (size_t)row0 * FDIM))[e];
    }
    __syncthreads();

    const int r  = t >> 3;            // 0..31 (row within block)
    const int d0 = (t & 7) * 4;       // 0,4,...,28
    float a0 = 0.f, a1 = 0.f, a2 = 0.f, a3 = 0.f;
#pragma unroll
    for (int k = 0; k < FDIM; k++) {
        const float xv = xs[r * FDIM + k];
        const float4 w4 = *(const float4*)&ws[k * EMBD + d0];
        a0 = fmaf(xv, w4.x, a0);
        a1 = fmaf(xv, w4.y, a1);
        a2 = fmaf(xv, w4.z, a2);
        a3 = fmaf(xv, w4.w, a3);
    }
    float4 o = make_float4(a0, a1, a2, a3);
    *(float4*)&xe[(size_t)(row0 + r) * EMBD + d0] = o;
}

// ---------------------------------------------------------------------------
// K2: centroid = mean(xe[:1024], axis=0); scale = 0.9 / max|x0 - centroid|
// One block of 1024 threads: warp w owns dim w.
// ---------------------------------------------------------------------------
__global__ __launch_bounds__(1024) void k2_stats(const float* __restrict__ xe) {
    __shared__ float cent[EMBD];
    __shared__ float wmax[EMBD];
    const int t = threadIdx.x;
    const int w = t >> 5, l = t & 31;

    float s = 0.f;
#pragma unroll
    for (int m = 0; m < 32; m++) s += xe[(size_t)(l + m * 32) * EMBD + w];
#pragma unroll
    for (int o = 16; o; o >>= 1) s += __shfl_xor_sync(0xffffffffu, s, o);
    if (l == 0) cent[w] = s * (1.0f / 1024.0f);
    __syncthreads();

    const float c = cent[w];
    float mx = 0.f;
#pragma unroll
    for (int m = 0; m < 32; m++)
        mx = fmaxf(mx, fabsf(xe[(size_t)(l + m * 32) * EMBD + w] - c));
#pragma unroll
    for (int o = 16; o; o >>= 1) mx = fmaxf(mx, __shfl_xor_sync(0xffffffffu, mx, o));
    if (l == 0) wmax[w] = mx;
    __syncthreads();

    if (t < EMBD) g_stats[t] = cent[t];
    if (t == 0) {
        float m2 = 0.f;
#pragma unroll
        for (int i = 0; i < EMBD; i++) m2 = fmaxf(m2, wmax[i]);
        g_stats[32] = 0.9f / m2;
    }
}

// ---------------------------------------------------------------------------
// K3: xg = (xe - centroid) * scale, stored transposed per graph, plus sq.
// One thread per row. Writes are coalesced across the warp (per-k columns).
// ---------------------------------------------------------------------------
__global__ __launch_bounds__(256) void k3_norm(const float* __restrict__ xe) {
    const int i = blockIdx.x * 256 + threadIdx.x;     // row id 0..32767
    const float scale = g_stats[32];
    const int g  = i >> 10;
    const int il = i & 1023;
    const float* row = xe + (size_t)i * EMBD;
    float* dstb = g_xgT + (size_t)g * (EMBD * NPG) + il;
    float s = 0.f;
#pragma unroll
    for (int k = 0; k < EMBD; k++) {
        const float v = (row[k] - g_stats[k]) * scale;
        dstb[k * NPG] = v;
        s = fmaf(v, v, s);
    }
    g_sq[i] = s;
}

// ---------------------------------------------------------------------------
// K4: per-graph pairwise 128x128 tiles. 256 threads, 8x8 register tile each,
// packed f32x2 FMA. Epilogue: D, sigmoid, and vectorized stores of
// edge_weight + src + dst (indices are pure functions of position).
// ---------------------------------------------------------------------------
__global__ __launch_bounds__(256) void k4_pair(float* __restrict__ out,
                                               const float* __restrict__ tptr,
                                               const float* __restrict__ thptr) {
    __shared__ float xiT[EMBD * 128];   // [k][i] 16 KB
    __shared__ float xjT[EMBD * 128];   // [k][j] 16 KB
    __shared__ float sqi[128], sqj[128];

    const int t  = threadIdx.x;
    const int g  = blockIdx.z;
    const int i0 = blockIdx.y * 128;
    const int j0 = blockIdx.x * 128;
    const float* base = g_xgT + (size_t)g * (EMBD * NPG);

    // load tiles: 32 k-rows x 128 floats = 1024 float4 each
    for (int e = t; e < 1024; e += 256) {
        const int k = e >> 5, c = e & 31;
        ((float4*)xiT)[e] = *(const float4*)(base + k * NPG + i0 + c * 4);
        ((float4*)xjT)[e] = *(const float4*)(base + k * NPG + j0 + c * 4);
    }
    if (t < 128)       sqi[t]       = g_sq[g * NPG + i0 + t];
    else               sqj[t - 128] = g_sq[g * NPG + j0 + (t - 128)];
    __syncthreads();

    const int ty = t >> 4, tx = t & 15;
    const int isub = ty * 8, jsub = tx * 8;

    unsigned long long acc[8][4];
#pragma unroll
    for (int r = 0; r < 8; r++)
#pragma unroll
        for (int c = 0; c < 4; c++) acc[r][c] = 0ull;

#pragma unroll
    for (int k = 0; k < EMBD; k++) {
        const float4 A0 = *(const float4*)&xiT[k * 128 + isub];
        const float4 A1 = *(const float4*)&xiT[k * 128 + isub + 4];
        const float4 B0 = *(const float4*)&xjT[k * 128 + jsub];
        const float4 B1 = *(const float4*)&xjT[k * 128 + jsub + 4];
        unsigned long long bp[4];
        bp[0] = pack2(B0.x, B0.y); bp[1] = pack2(B0.z, B0.w);
        bp[2] = pack2(B1.x, B1.y); bp[3] = pack2(B1.z, B1.w);
        const float av[8] = {A0.x, A0.y, A0.z, A0.w, A1.x, A1.y, A1.z, A1.w};
#pragma unroll
        for (int r = 0; r < 8; r++) {
            const unsigned long long as = pack2(av[r], av[r]);
#pragma unroll
            for (int c = 0; c < 4; c++) acc[r][c] = ffma2(as, bp[c], acc[r][c]);
        }
    }

    const float temp = *tptr;
    const float athr = fabsf(*thptr);
    const float jbasef = (float)(g * NPG + j0 + jsub);
    const float4 dst0 = make_float4(jbasef,        jbasef + 1.f, jbasef + 2.f, jbasef + 3.f);
    const float4 dst1 = make_float4(jbasef + 4.f,  jbasef + 5.f, jbasef + 6.f, jbasef + 7.f);

#pragma unroll
    for (int r = 0; r < 8; r++) {
        const int il = isub + r;                 // local i in tile
        const float si = sqi[il];
        float Av[8];
#pragma unroll
        for (int c = 0; c < 4; c++) {
            float d0, d1;
            unpack2(acc[r][c], d0, d1);
            const float sj0 = sqj[jsub + 2 * c];
            const float sj1 = sqj[jsub + 2 * c + 1];
            const float D0 = fmaxf(si + sj0 - 2.0f * d0, 0.0f);
            const float D1 = fmaxf(si + sj1 - 2.0f * d1, 0.0f);
            // sigmoid(temp*(athr - D)) = 1/(1 + exp(temp*(D - athr)))
            Av[2 * c]     = __fdividef(1.0f, 1.0f + __expf(temp * (D0 - athr)));
            Av[2 * c + 1] = __fdividef(1.0f, 1.0f + __expf(temp * (D1 - athr)));
        }
        const size_t eidx = (size_t)g * ((size_t)NPG * NPG)
                          + (size_t)(i0 + il) * NPG + (size_t)(j0 + jsub);
        // edge_weight
        *(float4*)(out + OFF_EW + eidx)     = make_float4(Av[0], Av[1], Av[2], Av[3]);
        *(float4*)(out + OFF_EW + eidx + 4) = make_float4(Av[4], Av[5], Av[6], Av[7]);
        // src: constant along the row
        const float fsrc = (float)(g * NPG + i0 + il);
        const float4 s4 = make_float4(fsrc, fsrc, fsrc, fsrc);
        *(float4*)(out + OFF_SRC + eidx)     = s4;
        *(float4*)(out + OFF_SRC + eidx + 4) = s4;
        // dst: j values
        *(float4*)(out + OFF_DST + eidx)     = dst0;
        *(float4*)(out + OFF_DST + eidx + 4) = dst1;
    }
}

// ---------------------------------------------------------------------------
extern "C" void kernel_launch(void* const* d_in, const int* in_sizes, int n_in,
                              void* d_out, int out_size) {
    const float* x     = (const float*)d_in[0];
    const float* W     = (const float*)d_in[1];
    const float* tptr  = (const float*)d_in[2];
    const float* thptr = (const float*)d_in[3];
    float* out = (float*)d_out;

    k1_gemm<<<NTOT / 32, 256>>>(x, W, out);
    k2_stats<<<1, 1024>>>(out);
    k3_norm<<<NTOT / 256, 256>>>(out);
    k4_pair<<<dim3(8, 8, NG), 256>>>(out, tptr, thptr);
}

// round 2
// speedup vs baseline: 1.5879x; 1.5879x over previous
#include <cuda_runtime.h>
#include <cstdint>

// Problem constants (fixed shapes)
#define NTOT 32768
#define FDIM 128
#define EMBD 32
#define NG   32
#define NPG  1024
// Output layout (all float32):
//   [0, 1048576)       xe
//   OFF_SRC            src (as float)
//   OFF_DST            dst (as float)
//   OFF_EW             edge_weight
#define OFF_SRC 1048576u
#define OFF_DST 34603008u
#define OFF_EW  68157440u

__device__ float g_xgT[NG * EMBD * NPG];   // [g][k][i]
__device__ float g_sq[NTOT];
__device__ float g_stats[33];              // [0..31]=centroid, [32]=scale

// ---------------------------------------------------------------------------
// packed f32x2 + streaming-store helpers
// ---------------------------------------------------------------------------
__device__ __forceinline__ unsigned long long pack2(float lo, float hi) {
    unsigned long long r;
    asm("mov.b64 %0, {%1, %2};" : "=l"(r) : "f"(lo), "f"(hi));
    return r;
}
__device__ __forceinline__ void unpack2(unsigned long long v, float& lo, float& hi) {
    asm("mov.b64 {%0, %1}, %2;" : "=f"(lo), "=f"(hi) : "l"(v));
}
__device__ __forceinline__ unsigned long long ffma2(unsigned long long a,
                                                    unsigned long long b,
                                                    unsigned long long c) {
    unsigned long long d;
    asm("fma.rn.f32x2 %0, %1, %2, %3;" : "=l"(d) : "l"(a), "l"(b), "l"(c));
    return d;
}
__device__ __forceinline__ void st_cs(float* p, float4 v) {
    asm volatile("st.global.cs.v4.f32 [%0], {%1,%2,%3,%4};"
                 :: "l"(p), "f"(v.x), "f"(v.y), "f"(v.z), "f"(v.w) : "memory");
}

// ---------------------------------------------------------------------------
// K1: xe = x @ W  (32768x128 @ 128x32)
// ---------------------------------------------------------------------------
__global__ __launch_bounds__(256) void k1_gemm(const float* __restrict__ x,
                                               const float* __restrict__ W,
                                               float* __restrict__ xe) {
    __shared__ float ws[FDIM * EMBD];
    __shared__ float xs[32 * FDIM];
    const int t = threadIdx.x;
    const int row0 = blockIdx.x * 32;

    for (int e = t; e < FDIM * EMBD; e += 256) ws[e] = W[e];
    for (int e = t; e < 1024; e += 256)
        ((float4*)xs)[e] = ((const float4*)(x + (size_t)row0 * FDIM))[e];
    __syncthreads();

    const int r  = t >> 3;
    const int d0 = (t & 7) * 4;
    float a0 = 0.f, a1 = 0.f, a2 = 0.f, a3 = 0.f;
#pragma unroll
    for (int k = 0; k < FDIM; k++) {
        const float xv = xs[r * FDIM + k];
        const float4 w4 = *(const float4*)&ws[k * EMBD + d0];
        a0 = fmaf(xv, w4.x, a0);
        a1 = fmaf(xv, w4.y, a1);
        a2 = fmaf(xv, w4.z, a2);
        a3 = fmaf(xv, w4.w, a3);
    }
    *(float4*)&xe[(size_t)(row0 + r) * EMBD + d0] = make_float4(a0, a1, a2, a3);
}

// ---------------------------------------------------------------------------
// K2: centroid + scale. 1024 threads; thread t holds row t entirely in regs.
// Butterfly shuffle reductions; pass 2 reuses the registers (no reread).
// ---------------------------------------------------------------------------
__global__ __launch_bounds__(1024) void k2_stats(const float* __restrict__ xe) {
    __shared__ float part[32 * 32];   // [warp][dim]
    __shared__ float cent[EMBD];
    const int t = threadIdx.x;
    const int w = t >> 5, l = t & 31;

    float v[EMBD];
#pragma unroll
    for (int q = 0; q < 8; q++) {
        const float4 f = ((const float4*)(xe + (size_t)t * EMBD))[q];
        v[4 * q] = f.x; v[4 * q + 1] = f.y; v[4 * q + 2] = f.z; v[4 * q + 3] = f.w;
    }

    // pass 1: per-dim sums
#pragma unroll
    for (int d = 0; d < EMBD; d++) {
        float s = v[d];
#pragma unroll
        for (int o = 16; o; o >>= 1) s += __shfl_xor_sync(0xffffffffu, s, o);
        if (l == 0) part[w * 32 + d] = s;
    }
    __syncthreads();
    if (w == 0) {
        float s = 0.f;
#pragma unroll
        for (int b = 0; b < 32; b++) s += part[b * 32 + l];
        const float c = s * (1.0f / 1024.0f);
        cent[l] = c;
        g_stats[l] = c;
    }
    __syncthreads();

    // pass 2: max |v - cent|
#pragma unroll
    for (int d = 0; d < EMBD; d++) {
        float m = fabsf(v[d] - cent[d]);
#pragma unroll
        for (int o = 16; o; o >>= 1) m = fmaxf(m, __shfl_xor_sync(0xffffffffu, m, o));
        if (l == 0) part[w * 32 + d] = m;
    }
    __syncthreads();
    if (w == 0) {
        float m = 0.f;
#pragma unroll
        for (int b = 0; b < 32; b++) m = fmaxf(m, part[b * 32 + l]);
#pragma unroll
        for (int o = 16; o; o >>= 1) m = fmaxf(m, __shfl_xor_sync(0xffffffffu, m, o));
        if (l == 0) g_stats[32] = 0.9f / m;
    }
}

// ---------------------------------------------------------------------------
// K3: normalize -> transposed per-graph layout + row norms
// ---------------------------------------------------------------------------
__global__ __launch_bounds__(256) void k3_norm(const float* __restrict__ xe) {
    const int i = blockIdx.x * 256 + threadIdx.x;
    const float scale = g_stats[32];
    const int g  = i >> 10;
    const int il = i & 1023;
    const float* row = xe + (size_t)i * EMBD;
    float* dstb = g_xgT + (size_t)g * (EMBD * NPG) + il;
    float s = 0.f;
#pragma unroll
    for (int k = 0; k < EMBD; k++) {
        const float v = (row[k] - g_stats[k]) * scale;
        dstb[k * NPG] = v;
        s = fmaf(v, v, s);
    }
    g_sq[i] = s;
}

// ---------------------------------------------------------------------------
// K4: 128x64 tiles, 256 threads, 8x4 register tile/thread, f32x2 FMA,
// forced 4 blocks/SM (50% occ). Streaming .cs stores for all 3 outputs.
// ---------------------------------------------------------------------------
__global__ __launch_bounds__(256, 4) void k4_pair(float* __restrict__ out,
                                                  const float* __restrict__ tptr,
                                                  const float* __restrict__ thptr) {
    __shared__ float xiT[EMBD * 128];   // [k][i] 16 KB
    __shared__ float xjT[EMBD * 64];    // [k][j] 8 KB
    __shared__ float sqi[128], sqj[64];

    const int t  = threadIdx.x;
    const int g  = blockIdx.z;
    const int i0 = blockIdx.y * 128;
    const int j0 = blockIdx.x * 64;
    const float* base = g_xgT + (size_t)g * (EMBD * NPG);

    // xiT: 32k x 128 = 1024 float4
    for (int e = t; e < 1024; e += 256) {
        const int k = e >> 5, c = e & 31;
        ((float4*)xiT)[e] = *(const float4*)(base + k * NPG + i0 + c * 4);
    }
    // xjT: 32k x 64 = 512 float4
    for (int e = t; e < 512; e += 256) {
        const int k = e >> 4, c = e & 15;
        ((float4*)xjT)[e] = *(const float4*)(base + k * NPG + j0 + c * 4);
    }
    if (t < 128)                   sqi[t]       = g_sq[g * NPG + i0 + t];
    else if (t < 192)              sqj[t - 128] = g_sq[g * NPG + j0 + (t - 128)];
    __syncthreads();

    const int ty = t >> 4, tx = t & 15;
    const int isub = ty * 8, jsub = tx * 4;

    unsigned long long acc[8][2];
#pragma unroll
    for (int r = 0; r < 8; r++) { acc[r][0] = 0ull; acc[r][1] = 0ull; }

#pragma unroll
    for (int k = 0; k < EMBD; k++) {
        const float4 A0 = *(const float4*)&xiT[k * 128 + isub];
        const float4 A1 = *(const float4*)&xiT[k * 128 + isub + 4];
        const float4 B  = *(const float4*)&xjT[k * 64 + jsub];
        const unsigned long long bp0 = pack2(B.x, B.y);
        const unsigned long long bp1 = pack2(B.z, B.w);
        const float av[8] = {A0.x, A0.y, A0.z, A0.w, A1.x, A1.y, A1.z, A1.w};
#pragma unroll
        for (int r = 0; r < 8; r++) {
            const unsigned long long as = pack2(av[r], av[r]);
            acc[r][0] = ffma2(as, bp0, acc[r][0]);
            acc[r][1] = ffma2(as, bp1, acc[r][1]);
        }
    }

    const float temp = *tptr;
    const float athr = fabsf(*thptr);
    const float sj0 = sqj[jsub], sj1 = sqj[jsub + 1];
    const float sj2 = sqj[jsub + 2], sj3 = sqj[jsub + 3];
    const float jbasef = (float)(g * NPG + j0 + jsub);
    const float4 dst4 = make_float4(jbasef, jbasef + 1.f, jbasef + 2.f, jbasef + 3.f);

#pragma unroll
    for (int r = 0; r < 8; r++) {
        const int il = isub + r;
        const float si = sqi[il];
        float d0, d1, d2, d3;
        unpack2(acc[r][0], d0, d1);
        unpack2(acc[r][1], d2, d3);
        const float D0 = fmaxf(si + sj0 - 2.0f * d0, 0.0f);
        const float D1 = fmaxf(si + sj1 - 2.0f * d1, 0.0f);
        const float D2 = fmaxf(si + sj2 - 2.0f * d2, 0.0f);
        const float D3 = fmaxf(si + sj3 - 2.0f * d3, 0.0f);
        float4 A4;
        A4.x = __fdividef(1.0f, 1.0f + __expf(temp * (D0 - athr)));
        A4.y = __fdividef(1.0f, 1.0f + __expf(temp * (D1 - athr)));
        A4.z = __fdividef(1.0f, 1.0f + __expf(temp * (D2 - athr)));
        A4.w = __fdividef(1.0f, 1.0f + __expf(temp * (D3 - athr)));

        const size_t eidx = (size_t)g * ((size_t)NPG * NPG)
                          + (size_t)(i0 + il) * NPG + (size_t)(j0 + jsub);
        st_cs(out + OFF_EW + eidx, A4);
        const float fsrc = (float)(g * NPG + i0 + il);
        st_cs(out + OFF_SRC + eidx, make_float4(fsrc, fsrc, fsrc, fsrc));
        st_cs(out + OFF_DST + eidx, dst4);
    }
}

// ---------------------------------------------------------------------------
extern "C" void kernel_launch(void* const* d_in, const int* in_sizes, int n_in,
                              void* d_out, int out_size) {
    const float* x     = (const float*)d_in[0];
    const float* W     = (const float*)d_in[1];
    const float* tptr  = (const float*)d_in[2];
    const float* thptr = (const float*)d_in[3];
    float* out = (float*)d_out;

    k1_gemm<<<NTOT / 32, 256>>>(x, W, out);
    k2_stats<<<1, 1024>>>(out);
    k3_norm<<<NTOT / 256, 256>>>(out);
    k4_pair<<<dim3(16, 8, NG), 256>>>(out, tptr, thptr);
}